// round 5
// baseline (speedup 1.0000x reference)
#include <cuda_runtime.h>
#include <cuda_fp16.h>

#define DIMC 128
#define HEADS 8
#define HD 16
#define HH 32
#define WW 32
#define ZZ 8
#define NPTS 8192   // 32*32*8
#define NXV 1024    // 16*16*4

typedef unsigned long long u64;

// Scratch (device globals)
__device__ float   g_stats_x[DIMC * 2];
__device__ float   g_stats_s[DIMC * 2];
__device__ __half2 g_q16[HEADS * NXV * 8];     // [head][m][8 half2]
__device__ __half2 g_k16[HEADS * NPTS * 8];    // [head][n][8 half2]
__device__ float   g_v32[HEADS * NPTS * HD];   // [head][n][16] fp32
__device__ float   g_oT[DIMC * NPTS];          // [j][n]

// ---- packed f32x2 helpers (sm_100+) --------------------------------------
__device__ __forceinline__ u64 pk2(float x) {
    u64 r; unsigned xi = __float_as_uint(x);
    asm("mov.b64 %0,{%1,%1};" : "=l"(r) : "r"(xi));
    return r;
}
__device__ __forceinline__ void ffma2(u64& d, u64 a, u64 b) {
    asm("fma.rn.f32x2 %0,%1,%2,%0;" : "+l"(d) : "l"(a), "l"(b));
}
__device__ __forceinline__ float2 up2(u64 v) {
    unsigned lo, hi;
    asm("mov.b64 {%0,%1},%2;" : "=r"(lo), "=r"(hi) : "l"(v));
    return make_float2(__uint_as_float(lo), __uint_as_float(hi));
}

// ---------------------------------------------------------------------------
// Kernel 1: instance-norm statistics
// ---------------------------------------------------------------------------
__global__ void stats_kernel(const float* __restrict__ x,
                             const float* __restrict__ skip) {
    int c = blockIdx.x;
    const float* src; int n; float* dst;
    if (c < DIMC) { src = x + c * NXV;              n = NXV;  dst = g_stats_x + c * 2; }
    else          { src = skip + (c - DIMC) * NPTS; n = NPTS; dst = g_stats_s + (c - DIMC) * 2; }

    float s = 0.f, s2 = 0.f;
    for (int i = threadIdx.x; i < n; i += 256) {
        float v = src[i];
        s += v; s2 += v * v;
    }
    __shared__ float sh1[8], sh2[8];
    #pragma unroll
    for (int o = 16; o; o >>= 1) {
        s  += __shfl_down_sync(0xffffffffu, s,  o);
        s2 += __shfl_down_sync(0xffffffffu, s2, o);
    }
    int wid = threadIdx.x >> 5, lid = threadIdx.x & 31;
    if (lid == 0) { sh1[wid] = s; sh2[wid] = s2; }
    __syncthreads();
    if (threadIdx.x == 0) {
        float ts = 0.f, ts2 = 0.f;
        #pragma unroll
        for (int i = 0; i < 8; i++) { ts += sh1[i]; ts2 += sh2[i]; }
        float mean = ts / n;
        float var  = ts2 / n - mean * mean;
        dst[0] = mean;
        dst[1] = rsqrtf(var + 1e-5f);
    }
}

// ---------------------------------------------------------------------------
// Kernel 2: K/V GEMM. Tile 64n x 128j, 256 thr, micro 4n x 8j with f32x2.
// Double-buffered smem, 1 barrier per k-iter (kc=16, 8 iters).
// K output fp16 packed; V output fp32. grid (128, 2).
// ---------------------------------------------------------------------------
__global__ __launch_bounds__(256) void kv_gemm(
        const float* __restrict__ skip,
        const float* __restrict__ Wk, const float* __restrict__ bk,
        const float* __restrict__ Wv, const float* __restrict__ bv) {
    const float* Wt = blockIdx.y ? Wv : Wk;
    const float* bt = blockIdx.y ? bv : bk;
    int n0 = blockIdx.x * 64;
    int tid = threadIdx.x;

    __shared__ float As[2][16][64];
    __shared__ float Bs[2][16][128];
    __shared__ float sm[DIMC], srs[DIMC];
    if (tid < 128) {
        sm[tid]  = g_stats_s[tid * 2];
        srs[tid] = g_stats_s[tid * 2 + 1];
    }
    __syncthreads();

    int tx = tid & 15, ty = tid >> 4;

    u64 acc[4][4];
    #pragma unroll
    for (int i = 0; i < 4; i++)
        #pragma unroll
        for (int j = 0; j < 4; j++) acc[i][j] = 0ull;

    float  ar[4];
    float4 br[2];

    // prefetch iter 0
    #pragma unroll
    for (int i = 0; i < 4; i++) {
        int idx = i * 256 + tid;
        int kk = idx >> 6, r = idx & 63;
        ar[i] = (skip[kk * NPTS + n0 + r] - sm[kk]) * srs[kk];
    }
    #pragma unroll
    for (int i = 0; i < 2; i++) {
        int idx = i * 256 + tid;
        int kk = idx >> 5, r4 = idx & 31;
        br[i] = *(const float4*)&Wt[kk * DIMC + r4 * 4];
    }
    #pragma unroll
    for (int i = 0; i < 4; i++) {
        int idx = i * 256 + tid;
        As[0][idx >> 6][idx & 63] = ar[i];
    }
    #pragma unroll
    for (int i = 0; i < 2; i++) {
        int idx = i * 256 + tid;
        *(float4*)&Bs[0][idx >> 5][(idx & 31) * 4] = br[i];
    }
    __syncthreads();

    for (int it = 0; it < 8; it++) {
        int cur = it & 1;
        if (it < 7) {
            int c0 = (it + 1) * 16;
            #pragma unroll
            for (int i = 0; i < 4; i++) {
                int idx = i * 256 + tid;
                int kk = c0 + (idx >> 6), r = idx & 63;
                ar[i] = (skip[kk * NPTS + n0 + r] - sm[kk]) * srs[kk];
            }
            #pragma unroll
            for (int i = 0; i < 2; i++) {
                int idx = i * 256 + tid;
                int kk = c0 + (idx >> 5), r4 = idx & 31;
                br[i] = *(const float4*)&Wt[kk * DIMC + r4 * 4];
            }
        }
        #pragma unroll
        for (int kk = 0; kk < 16; kk++) {
            float4 a4 = *(const float4*)&As[cur][kk][ty * 4];
            u64 pa0 = pk2(a4.x), pa1 = pk2(a4.y), pa2 = pk2(a4.z), pa3 = pk2(a4.w);
            ulonglong2 b01 = *(const ulonglong2*)&Bs[cur][kk][tx * 8];
            ulonglong2 b23 = *(const ulonglong2*)&Bs[cur][kk][tx * 8 + 4];
            ffma2(acc[0][0], pa0, b01.x); ffma2(acc[0][1], pa0, b01.y);
            ffma2(acc[0][2], pa0, b23.x); ffma2(acc[0][3], pa0, b23.y);
            ffma2(acc[1][0], pa1, b01.x); ffma2(acc[1][1], pa1, b01.y);
            ffma2(acc[1][2], pa1, b23.x); ffma2(acc[1][3], pa1, b23.y);
            ffma2(acc[2][0], pa2, b01.x); ffma2(acc[2][1], pa2, b01.y);
            ffma2(acc[2][2], pa2, b23.x); ffma2(acc[2][3], pa2, b23.y);
            ffma2(acc[3][0], pa3, b01.x); ffma2(acc[3][1], pa3, b01.y);
            ffma2(acc[3][2], pa3, b23.x); ffma2(acc[3][3], pa3, b23.y);
        }
        if (it < 7) {
            int nb = 1 - cur;
            #pragma unroll
            for (int i = 0; i < 4; i++) {
                int idx = i * 256 + tid;
                As[nb][idx >> 6][idx & 63] = ar[i];
            }
            #pragma unroll
            for (int i = 0; i < 2; i++) {
                int idx = i * 256 + tid;
                *(float4*)&Bs[nb][idx >> 5][(idx & 31) * 4] = br[i];
            }
            __syncthreads();
        }
    }

    float bb[8];
    #pragma unroll
    for (int p = 0; p < 8; p++) bb[p] = bt[tx * 8 + p];
    int head = tx >> 1;
    int half = tx & 1;

    if (blockIdx.y == 0) {       // K -> fp16
        #pragma unroll
        for (int i = 0; i < 4; i++) {
            int n = n0 + ty * 4 + i;
            __half2* op = g_k16 + (head * NPTS + n) * 8 + half * 4;
            #pragma unroll
            for (int p = 0; p < 4; p++) {
                float2 f = up2(acc[i][p]);
                op[p] = __floats2half2_rn(f.x + bb[2 * p], f.y + bb[2 * p + 1]);
            }
        }
    } else {                     // V -> fp32
        #pragma unroll
        for (int i = 0; i < 4; i++) {
            int n = n0 + ty * 4 + i;
            float* op = g_v32 + (head * NPTS + n) * 16 + half * 8;
            #pragma unroll
            for (int p = 0; p < 4; p++) {
                float2 f = up2(acc[i][p]);
                op[2 * p]     = f.x + bb[2 * p];
                op[2 * p + 1] = f.y + bb[2 * p + 1];
            }
        }
    }
}

// ---------------------------------------------------------------------------
// Kernel 3: Q GEMM (1024 unique voxels). Tile 16n x 128j, micro 1n x 8j,
// grid 64, scale 0.25 folded. fp16 packed output.
// ---------------------------------------------------------------------------
__global__ __launch_bounds__(256) void q_gemm(
        const float* __restrict__ x,
        const float* __restrict__ Wq, const float* __restrict__ bq) {
    int n0 = blockIdx.x * 16;
    int tid = threadIdx.x;

    __shared__ float As[2][16][16];
    __shared__ float Bs[2][16][128];
    __shared__ float sm[DIMC], srs[DIMC];
    if (tid < 128) {
        sm[tid]  = g_stats_x[tid * 2];
        srs[tid] = g_stats_x[tid * 2 + 1];
    }
    __syncthreads();

    int tx = tid & 15, ty = tid >> 4;

    u64 acc[4];
    #pragma unroll
    for (int p = 0; p < 4; p++) acc[p] = 0ull;

    float  ar;
    float4 br[2];

    {
        int kk = tid >> 4, r = tid & 15;
        ar = (x[kk * NXV + n0 + r] - sm[kk]) * srs[kk];
        #pragma unroll
        for (int i = 0; i < 2; i++) {
            int idx = i * 256 + tid;
            int kk2 = idx >> 5, r4 = idx & 31;
            br[i] = *(const float4*)&Wq[kk2 * DIMC + r4 * 4];
        }
        As[0][kk][r] = ar;
        #pragma unroll
        for (int i = 0; i < 2; i++) {
            int idx = i * 256 + tid;
            *(float4*)&Bs[0][idx >> 5][(idx & 31) * 4] = br[i];
        }
    }
    __syncthreads();

    for (int it = 0; it < 8; it++) {
        int cur = it & 1;
        if (it < 7) {
            int c0 = (it + 1) * 16;
            int kk = c0 + (tid >> 4), r = tid & 15;
            ar = (x[kk * NXV + n0 + r] - sm[kk]) * srs[kk];
            #pragma unroll
            for (int i = 0; i < 2; i++) {
                int idx = i * 256 + tid;
                int kk2 = c0 + (idx >> 5), r4 = idx & 31;
                br[i] = *(const float4*)&Wq[kk2 * DIMC + r4 * 4];
            }
        }
        #pragma unroll
        for (int kk = 0; kk < 16; kk++) {
            u64 pa = pk2(As[cur][kk][ty]);
            ulonglong2 b01 = *(const ulonglong2*)&Bs[cur][kk][tx * 8];
            ulonglong2 b23 = *(const ulonglong2*)&Bs[cur][kk][tx * 8 + 4];
            ffma2(acc[0], pa, b01.x); ffma2(acc[1], pa, b01.y);
            ffma2(acc[2], pa, b23.x); ffma2(acc[3], pa, b23.y);
        }
        if (it < 7) {
            int nb = 1 - cur;
            As[nb][tid >> 4][tid & 15] = ar;
            #pragma unroll
            for (int i = 0; i < 2; i++) {
                int idx = i * 256 + tid;
                *(float4*)&Bs[nb][idx >> 5][(idx & 31) * 4] = br[i];
            }
            __syncthreads();
        }
    }

    int head = tx >> 1;
    int half = tx & 1;
    int n = n0 + ty;
    __half2* op = g_q16 + (head * NXV + n) * 8 + half * 4;
    #pragma unroll
    for (int p = 0; p < 4; p++) {
        float2 f = up2(acc[p]);
        int j = tx * 8 + 2 * p;
        op[p] = __floats2half2_rn((f.x + bq[j]) * 0.25f,
                                  (f.y + bq[j + 1]) * 0.25f);
    }
}

// ---------------------------------------------------------------------------
// Kernel 4: neighborhood attention. Tile 4x4x8 = 128 pts, 256 thr:
// 2 threads per point, lane pairs (tid, tid^1) split the 25 (jh,jw) columns
// 13/12 and reduce via shfl_xor(1). Halo 8x8x8: K fp16 (16KB) + V fp32
// (32KB) swizzled + bias (2.9KB) = ~51KB. grid (8,8,8) = 512 blocks.
// No-max softmax (logits O(0.1)); V accumulated with fma.rn.f32x2.
// ---------------------------------------------------------------------------
__global__ __launch_bounds__(256, 4) void attn_kernel(const float* __restrict__ rpb) {
    extern __shared__ float smem[];
    float4* sk4 = (float4*)smem;              // 1024 float4 (fp16 K)
    float4* sv4 = sk4 + 1024;                 // 2048 float4 (fp32 V)
    float*  sb  = (float*)(sv4 + 2048);       // 729 bias

    int head = blockIdx.z;
    int h0 = blockIdx.x * 4, w0 = blockIdx.y * 4;
    int hlo = min(max(h0 - 2, 0), HH - 5);
    int wlo = min(max(w0 - 2, 0), WW - 5);
    int tid = threadIdx.x;

    for (int i = tid; i < 729; i += 256) sb[i] = rpb[head * 729 + i];

    const float4* gk4 = (const float4*)g_k16 + head * (NPTS * 2);
    const float4* gv4 = (const float4*)g_v32 + head * (NPTS * 4);
    #pragma unroll
    for (int it = 0; it < 4; it++) {
        int idx = it * 256 + tid;
        int d = idx & 1, pos = idx >> 1;
        int z1 = pos & 7, col = pos >> 3, wwi = col & 7, wh = col >> 3;
        int n = min(hlo + wh, HH - 1) * 256 + min(wlo + wwi, WW - 1) * 8 + z1;
        sk4[pos * 2 + (d ^ (((pos >> 1) ^ (pos >> 2)) & 1))] = gk4[n * 2 + d];
    }
    #pragma unroll
    for (int it = 0; it < 8; it++) {
        int idx = it * 256 + tid;
        int d = idx & 3, pos = idx >> 2;
        int z1 = pos & 7, col = pos >> 3, wwi = col & 7, wh = col >> 3;
        int n = min(hlo + wh, HH - 1) * 256 + min(wlo + wwi, WW - 1) * 8 + z1;
        sv4[pos * 4 + ((d ^ (pos >> 1)) & 3)] = gv4[n * 4 + d];
    }
    __syncthreads();

    int split = tid & 1;
    int pt = tid >> 1;
    int z = pt & 7, dw = (pt >> 3) & 3, dh = pt >> 5;
    int h = h0 + dh, w = w0 + dw;
    int sh = min(max(h - 2, 0), HH - 5);
    int sw = min(max(w - 2, 0), WW - 5);
    int sz = min(max(z - 2, 0), ZZ - 5);
    int m = (h >> 1) * 64 + (w >> 1) * 4 + (z >> 1);

    __half2 q2[8];
    {
        const float4* gq4 = (const float4*)g_q16 + (head * NXV + m) * 2;
        float4 qA = gq4[0], qB = gq4[1];
        const __half2* qa = (const __half2*)&qA;
        const __half2* qb = (const __half2*)&qB;
        #pragma unroll
        for (int i = 0; i < 4; i++) { q2[i] = qa[i]; q2[4 + i] = qb[i]; }
    }

    int bh = sh - h + 4, bw = sw - w + 4, bz = sz - z + 4;

    float sum = 0.f;
    u64 acc[8];
    #pragma unroll
    for (int k = 0; k < 8; k++) acc[k] = 0ull;

    int jh = 0, jw = split;
    for (int c = split; c < 25; c += 2) {
        int colg = (sh + jh - hlo) * 8 + (sw + jw - wlo);
        int posb = colg * 8 + sz;
        const float* bp = sb + (bh + jh) * 81 + (bw + jw) * 9 + bz;
        #pragma unroll
        for (int jz = 0; jz < 5; jz++) {
            int pos = posb + jz;
            int kb = ((pos >> 1) ^ (pos >> 2)) & 1;
            float4 kA = sk4[pos * 2 + kb];          // dims 0-7
            float4 kB = sk4[pos * 2 + (1 ^ kb)];    // dims 8-15
            const __half2* ka = (const __half2*)&kA;
            const __half2* kb2 = (const __half2*)&kB;
            __half2 s0 = __hmul2(q2[0], ka[0]);
            __half2 s1 = __hmul2(q2[1], ka[1]);
            s0 = __hfma2(q2[2], ka[2], s0);
            s1 = __hfma2(q2[3], ka[3], s1);
            s0 = __hfma2(q2[4], kb2[0], s0);
            s1 = __hfma2(q2[5], kb2[1], s1);
            s0 = __hfma2(q2[6], kb2[2], s0);
            s1 = __hfma2(q2[7], kb2[3], s1);
            float2 lf = __half22float2(__hadd2(s0, s1));
            float l = bp[jz] + lf.x + lf.y;
            float p = __expf(l);
            sum += p;
            u64 pp = pk2(p);
            int r = (pos >> 1) & 3;
            #pragma unroll
            for (int d = 0; d < 4; d++) {
                ulonglong2 v2 = *(const ulonglong2*)&sv4[pos * 4 + (d ^ r)];
                ffma2(acc[2 * d],     pp, v2.x);
                ffma2(acc[2 * d + 1], pp, v2.y);
            }
        }
        jw += 2;
        if (jw >= 5) { jw -= 5; jh++; }
    }

    // pairwise reduction across (even, odd) lanes
    float of[16];
    #pragma unroll
    for (int k = 0; k < 8; k++) {
        float2 f = up2(acc[k]);
        of[2 * k] = f.x; of[2 * k + 1] = f.y;
    }
    sum += __shfl_xor_sync(0xffffffffu, sum, 1);
    float inv = 1.f / sum;
    int base = split ? 8 : 0;    // even lane owns dims 0-7, odd owns 8-15
    float res[8];
    #pragma unroll
    for (int d = 0; d < 16; d++) {
        float o = __shfl_xor_sync(0xffffffffu, of[d], 1);
        if (d >= base && d < base + 8) res[d - base] = (of[d] + o) * inv;
    }
    int n = h * 256 + w * 8 + z;
    #pragma unroll
    for (int d = 0; d < 8; d++)
        g_oT[(head * HD + base + d) * NPTS + n] = res[d];
}

// ---------------------------------------------------------------------------
// Kernel 5: output projection. Tile 64c x 64n, 256 thr, micro 8c(4 pairs)x2n
// with f32x2 (A c-pairs native from LDS.128, B scalars packed).
// grid (128 n-tiles, 2 c-tiles). Double-buffered, kc=16.
// ---------------------------------------------------------------------------
__global__ __launch_bounds__(256) void proj_gemm(
        const float* __restrict__ Wo, const float* __restrict__ bo,
        float* __restrict__ outp) {
    int n0 = blockIdx.x * 64;
    int c0 = blockIdx.y * 64;
    int tid = threadIdx.x;

    __shared__ float As[2][16][64];   // Wo[j][c-slice]
    __shared__ float Bs[2][16][64];   // oT[j][n-slice]

    int tx = tid & 31, ty = tid >> 5;   // tx: n-pair (32), ty: c-octet (8)

    u64 acc[4][2];
    #pragma unroll
    for (int i = 0; i < 4; i++) { acc[i][0] = 0ull; acc[i][1] = 0ull; }

    float4 arA, arB;
    {
        int kk = tid >> 4, r4 = tid & 15;
        arA = *(const float4*)&Wo[kk * DIMC + c0 + r4 * 4];
        arB = *(const float4*)&g_oT[kk * NPTS + n0 + r4 * 4];
        *(float4*)&As[0][kk][r4 * 4] = arA;
        *(float4*)&Bs[0][kk][r4 * 4] = arB;
    }
    __syncthreads();

    for (int it = 0; it < 8; it++) {
        int cur = it & 1;
        if (it < 7) {
            int j0 = (it + 1) * 16;
            int kk = j0 + (tid >> 4), r4 = tid & 15;
            arA = *(const float4*)&Wo[kk * DIMC + c0 + r4 * 4];
            arB = *(const float4*)&g_oT[kk * NPTS + n0 + r4 * 4];
        }
        #pragma unroll
        for (int kk = 0; kk < 16; kk++) {
            ulonglong2 ca = *(const ulonglong2*)&As[cur][kk][ty * 8];
            ulonglong2 cb = *(const ulonglong2*)&As[cur][kk][ty * 8 + 4];
            float2 b2 = *(const float2*)&Bs[cur][kk][tx * 2];
            u64 pb0 = pk2(b2.x), pb1 = pk2(b2.y);
            ffma2(acc[0][0], ca.x, pb0); ffma2(acc[0][1], ca.x, pb1);
            ffma2(acc[1][0], ca.y, pb0); ffma2(acc[1][1], ca.y, pb1);
            ffma2(acc[2][0], cb.x, pb0); ffma2(acc[2][1], cb.x, pb1);
            ffma2(acc[3][0], cb.y, pb0); ffma2(acc[3][1], cb.y, pb1);
        }
        if (it < 7) {
            int nb = 1 - cur;
            int kk = tid >> 4, r4 = tid & 15;
            *(float4*)&As[nb][kk][r4 * 4] = arA;
            *(float4*)&Bs[nb][kk][r4 * 4] = arB;
            __syncthreads();
        }
    }

    #pragma unroll
    for (int cp = 0; cp < 4; cp++) {
        #pragma unroll
        for (int j = 0; j < 2; j++) {
            float2 f = up2(acc[cp][j]);
            int cA = c0 + ty * 8 + cp * 2;
            int nn = n0 + tx * 2 + j;
            outp[cA * NPTS + nn]       = f.x + bo[cA];
            outp[(cA + 1) * NPTS + nn] = f.y + bo[cA + 1];
        }
    }
}

// ---------------------------------------------------------------------------
extern "C" void kernel_launch(void* const* d_in, const int* in_sizes, int n_in,
                              void* d_out, int out_size) {
    const float* x    = (const float*)d_in[0];
    const float* skip = (const float*)d_in[1];
    const float* Wq   = (const float*)d_in[2];
    const float* bq   = (const float*)d_in[3];
    const float* Wk   = (const float*)d_in[4];
    const float* bk   = (const float*)d_in[5];
    const float* Wv   = (const float*)d_in[6];
    const float* bv   = (const float*)d_in[7];
    const float* rpb  = (const float*)d_in[8];
    const float* Wo   = (const float*)d_in[9];
    const float* bo   = (const float*)d_in[10];
    float* outp = (float*)d_out;

    const int attn_smem = 1024 * 16 + 2048 * 16 + 736 * 4;   // ~52KB
    cudaFuncSetAttribute(attn_kernel, cudaFuncAttributeMaxDynamicSharedMemorySize,
                         attn_smem);

    stats_kernel<<<256, 256>>>(x, skip);
    kv_gemm<<<dim3(128, 2), 256>>>(skip, Wk, bk, Wv, bv);
    q_gemm<<<64, 256>>>(x, Wq, bq);
    attn_kernel<<<dim3(8, 8, 8), 256, attn_smem>>>(rpb);
    proj_gemm<<<dim3(128, 2), 256>>>(Wo, bo, outp);
}

// round 8
// speedup vs baseline: 1.6621x; 1.6621x over previous
#include <cuda_runtime.h>
#include <cuda_fp16.h>

#define DIMC 128
#define HEADS 8
#define HD 16
#define HH 32
#define WW 32
#define ZZ 8
#define NPTS 8192   // 32*32*8
#define NXV 1024    // 16*16*4

typedef unsigned long long u64;

// Scratch (device globals)
__device__ float   g_stats_x[DIMC * 2];
__device__ float   g_stats_s[DIMC * 2];
__device__ __half2 g_q16[HEADS * NXV * 8];     // [head][m][8 half2]
__device__ __half2 g_k16[HEADS * NPTS * 8];    // [head][n][8 half2]
__device__ __half2 g_v16[HEADS * NPTS * 8];    // [head][n][8 half2]
__device__ float   g_oT[DIMC * NPTS];          // [j][n]

// ---- packed f32x2 helpers (sm_100+) --------------------------------------
__device__ __forceinline__ u64 pk2(float x) {
    u64 r; unsigned xi = __float_as_uint(x);
    asm("mov.b64 %0,{%1,%1};" : "=l"(r) : "r"(xi));
    return r;
}
__device__ __forceinline__ void ffma2(u64& d, u64 a, u64 b) {
    asm("fma.rn.f32x2 %0,%1,%2,%0;" : "+l"(d) : "l"(a), "l"(b));
}
__device__ __forceinline__ float2 up2(u64 v) {
    unsigned lo, hi;
    asm("mov.b64 {%0,%1},%2;" : "=r"(lo), "=r"(hi) : "l"(v));
    return make_float2(__uint_as_float(lo), __uint_as_float(hi));
}

// ---------------------------------------------------------------------------
// Kernel 1: instance-norm statistics
// ---------------------------------------------------------------------------
__global__ void stats_kernel(const float* __restrict__ x,
                             const float* __restrict__ skip) {
    int c = blockIdx.x;
    const float* src; int n; float* dst;
    if (c < DIMC) { src = x + c * NXV;              n = NXV;  dst = g_stats_x + c * 2; }
    else          { src = skip + (c - DIMC) * NPTS; n = NPTS; dst = g_stats_s + (c - DIMC) * 2; }

    float s = 0.f, s2 = 0.f;
    for (int i = threadIdx.x; i < n; i += 256) {
        float v = src[i];
        s += v; s2 += v * v;
    }
    __shared__ float sh1[8], sh2[8];
    #pragma unroll
    for (int o = 16; o; o >>= 1) {
        s  += __shfl_down_sync(0xffffffffu, s,  o);
        s2 += __shfl_down_sync(0xffffffffu, s2, o);
    }
    int wid = threadIdx.x >> 5, lid = threadIdx.x & 31;
    if (lid == 0) { sh1[wid] = s; sh2[wid] = s2; }
    __syncthreads();
    if (threadIdx.x == 0) {
        float ts = 0.f, ts2 = 0.f;
        #pragma unroll
        for (int i = 0; i < 8; i++) { ts += sh1[i]; ts2 += sh2[i]; }
        float mean = ts / n;
        float var  = ts2 / n - mean * mean;
        dst[0] = mean;
        dst[1] = rsqrtf(var + 1e-5f);
    }
}

// ---------------------------------------------------------------------------
// Kernel 2: fused Q/K/V projection GEMM, ONE launch, grid 272:
//   blocks [0,128)   : K tiles  (skip, Wk -> g_k16)
//   blocks [128,256) : V tiles  (skip, Wv -> g_v16)
//   blocks [256,272) : Q tiles  (x,    Wq -> g_q16, scale 0.25)
// Tile 64n x 128j, 256 thr, micro 4n x 8j with f32x2, double-buffered kc=16.
// Output packed fp16 [head][n][8 half2].
// ---------------------------------------------------------------------------
__global__ __launch_bounds__(256) void qkv_gemm(
        const float* __restrict__ x,    const float* __restrict__ skip,
        const float* __restrict__ Wq,   const float* __restrict__ bq,
        const float* __restrict__ Wk,   const float* __restrict__ bk,
        const float* __restrict__ Wv,   const float* __restrict__ bv) {
    int bid = blockIdx.x;
    const float* src; const float* Wt; const float* bt; const float* stats;
    __half2* outp; int strideN; float scale; int n0;
    if (bid < 128) {
        src = skip; Wt = Wk; bt = bk; stats = g_stats_s;
        outp = g_k16; strideN = NPTS; scale = 1.f; n0 = bid * 64;
    } else if (bid < 256) {
        src = skip; Wt = Wv; bt = bv; stats = g_stats_s;
        outp = g_v16; strideN = NPTS; scale = 1.f; n0 = (bid - 128) * 64;
    } else {
        src = x; Wt = Wq; bt = bq; stats = g_stats_x;
        outp = g_q16; strideN = NXV; scale = 0.25f; n0 = (bid - 256) * 64;
    }
    int tid = threadIdx.x;

    __shared__ float As[2][16][64];
    __shared__ float Bs[2][16][128];
    __shared__ float sm[DIMC], srs[DIMC];
    if (tid < 128) {
        sm[tid]  = stats[tid * 2];
        srs[tid] = stats[tid * 2 + 1];
    }
    __syncthreads();

    int tx = tid & 15, ty = tid >> 4;

    u64 acc[4][4];
    #pragma unroll
    for (int i = 0; i < 4; i++)
        #pragma unroll
        for (int j = 0; j < 4; j++) acc[i][j] = 0ull;

    float  ar[4];
    float4 br[2];

    // prefetch iter 0
    #pragma unroll
    for (int i = 0; i < 4; i++) {
        int idx = i * 256 + tid;
        int kk = idx >> 6, r = idx & 63;
        ar[i] = (src[kk * strideN + n0 + r] - sm[kk]) * srs[kk];
    }
    #pragma unroll
    for (int i = 0; i < 2; i++) {
        int idx = i * 256 + tid;
        int kk = idx >> 5, r4 = idx & 31;
        br[i] = *(const float4*)&Wt[kk * DIMC + r4 * 4];
    }
    #pragma unroll
    for (int i = 0; i < 4; i++) {
        int idx = i * 256 + tid;
        As[0][idx >> 6][idx & 63] = ar[i];
    }
    #pragma unroll
    for (int i = 0; i < 2; i++) {
        int idx = i * 256 + tid;
        *(float4*)&Bs[0][idx >> 5][(idx & 31) * 4] = br[i];
    }
    __syncthreads();

    for (int it = 0; it < 8; it++) {
        int cur = it & 1;
        if (it < 7) {
            int c0 = (it + 1) * 16;
            #pragma unroll
            for (int i = 0; i < 4; i++) {
                int idx = i * 256 + tid;
                int kk = c0 + (idx >> 6), r = idx & 63;
                ar[i] = (src[kk * strideN + n0 + r] - sm[kk]) * srs[kk];
            }
            #pragma unroll
            for (int i = 0; i < 2; i++) {
                int idx = i * 256 + tid;
                int kk = c0 + (idx >> 5), r4 = idx & 31;
                br[i] = *(const float4*)&Wt[kk * DIMC + r4 * 4];
            }
        }
        #pragma unroll
        for (int kk = 0; kk < 16; kk++) {
            float4 a4 = *(const float4*)&As[cur][kk][ty * 4];
            u64 pa0 = pk2(a4.x), pa1 = pk2(a4.y), pa2 = pk2(a4.z), pa3 = pk2(a4.w);
            ulonglong2 b01 = *(const ulonglong2*)&Bs[cur][kk][tx * 8];
            ulonglong2 b23 = *(const ulonglong2*)&Bs[cur][kk][tx * 8 + 4];
            ffma2(acc[0][0], pa0, b01.x); ffma2(acc[0][1], pa0, b01.y);
            ffma2(acc[0][2], pa0, b23.x); ffma2(acc[0][3], pa0, b23.y);
            ffma2(acc[1][0], pa1, b01.x); ffma2(acc[1][1], pa1, b01.y);
            ffma2(acc[1][2], pa1, b23.x); ffma2(acc[1][3], pa1, b23.y);
            ffma2(acc[2][0], pa2, b01.x); ffma2(acc[2][1], pa2, b01.y);
            ffma2(acc[2][2], pa2, b23.x); ffma2(acc[2][3], pa2, b23.y);
            ffma2(acc[3][0], pa3, b01.x); ffma2(acc[3][1], pa3, b01.y);
            ffma2(acc[3][2], pa3, b23.x); ffma2(acc[3][3], pa3, b23.y);
        }
        if (it < 7) {
            int nb = 1 - cur;
            #pragma unroll
            for (int i = 0; i < 4; i++) {
                int idx = i * 256 + tid;
                As[nb][idx >> 6][idx & 63] = ar[i];
            }
            #pragma unroll
            for (int i = 0; i < 2; i++) {
                int idx = i * 256 + tid;
                *(float4*)&Bs[nb][idx >> 5][(idx & 31) * 4] = br[i];
            }
            __syncthreads();
        }
    }

    float bb[8];
    #pragma unroll
    for (int p = 0; p < 8; p++) bb[p] = bt[tx * 8 + p];
    int head = tx >> 1;
    int half = tx & 1;
    #pragma unroll
    for (int i = 0; i < 4; i++) {
        int n = n0 + ty * 4 + i;
        __half2* op = outp + (head * strideN + n) * 8 + half * 4;
        #pragma unroll
        for (int p = 0; p < 4; p++) {
            float2 f = up2(acc[i][p]);
            op[p] = __floats2half2_rn((f.x + bb[2 * p]) * scale,
                                      (f.y + bb[2 * p + 1]) * scale);
        }
    }
}

// ---------------------------------------------------------------------------
// Kernel 3: neighborhood attention (R3 config — known 27.7us).
// Tile 4(h) x 8(w) x 8(z) = 256 threads, 1 thread per point.
// Halo 8x12x8 = 768 positions of fp16 k/v in swizzled smem (~52KB).
// No-max softmax (logits are O(0.1)), fp32 accumulator.
// grid (8 hblk, 4 wblk, 8 heads).
// ---------------------------------------------------------------------------
#define WH 12   // w halo extent
__global__ __launch_bounds__(256, 4) void attn_kernel(const float* __restrict__ rpb) {
    extern __shared__ float smem[];
    float4* sk4 = (float4*)smem;              // 1536 float4 (768 pos * 2)
    float4* sv4 = sk4 + 1536;                 // 1536 float4
    float*  sb  = (float*)(sv4 + 1536);       // 729 bias

    int head = blockIdx.z;
    int h0 = blockIdx.x * 4, w0 = blockIdx.y * 8;
    int hlo = min(max(h0 - 2, 0), HH - 5);
    int wlo = min(max(w0 - 2, 0), WW - 5);
    int tid = threadIdx.x;

    for (int i = tid; i < 729; i += 256) sb[i] = rpb[head * 729 + i];

    const float4* gk4 = (const float4*)g_k16 + head * (NPTS * 2);
    const float4* gv4 = (const float4*)g_v16 + head * (NPTS * 2);
    #pragma unroll
    for (int it = 0; it < 6; it++) {
        int idx = it * 256 + tid;             // 1536 (pos,d4) pairs
        int d4 = idx & 1, pos = idx >> 1;
        int col = pos >> 3, z1 = pos & 7;
        int wh = col / WH, wwi = col - wh * WH;
        int gh = min(hlo + wh, HH - 1);
        int gw = min(wlo + wwi, WW - 1);
        int n = gh * 256 + gw * 8 + z1;
        int s = pos * 2 + (d4 ^ (col & 1));   // XOR swizzle
        sk4[s] = gk4[n * 2 + d4];
        sv4[s] = gv4[n * 2 + d4];
    }
    __syncthreads();

    int z = tid & 7, dw = (tid >> 3) & 7, dh = tid >> 6;
    int h = h0 + dh, w = w0 + dw;
    int sh = min(max(h - 2, 0), HH - 5);
    int sw = min(max(w - 2, 0), WW - 5);
    int sz = min(max(z - 2, 0), ZZ - 5);
    int m = (h >> 1) * 64 + (w >> 1) * 4 + (z >> 1);

    __half2 q2[8];
    {
        const float4* gq4 = (const float4*)g_q16 + (head * NXV + m) * 2;
        float4 qA = gq4[0], qB = gq4[1];
        const __half2* qa = (const __half2*)&qA;
        const __half2* qb = (const __half2*)&qB;
        #pragma unroll
        for (int i = 0; i < 4; i++) { q2[i] = qa[i]; q2[4 + i] = qb[i]; }
    }

    int bh = sh - h + 4, bw = sw - w + 4, bz = sz - z + 4;

    float sum = 0.f;
    float acc[16];
    #pragma unroll
    for (int d = 0; d < 16; d++) acc[d] = 0.f;

    for (int jh = 0; jh < 5; jh++) {
        int colh = (sh + jh - hlo) * WH;
        const float* bph = sb + (bh + jh) * 81 + bz;
        for (int jw = 0; jw < 5; jw++) {
            int col = colh + (sw + jw - wlo);
            int e = col & 1;
            const float4* kp = sk4 + col * 16 + sz * 2;
            const float4* vp = sv4 + col * 16 + sz * 2;
            const float* bp = bph + (bw + jw) * 9;
            #pragma unroll
            for (int jz = 0; jz < 5; jz++) {
                float4 kA = kp[jz * 2 + e];
                float4 kB = kp[jz * 2 + 1 - e];
                const __half2* ka = (const __half2*)&kA;
                const __half2* kb = (const __half2*)&kB;
                __half2 s0 = __hmul2(q2[0], ka[0]);
                __half2 s1 = __hmul2(q2[1], ka[1]);
                s0 = __hfma2(q2[2], ka[2], s0);
                s1 = __hfma2(q2[3], ka[3], s1);
                s0 = __hfma2(q2[4], kb[0], s0);
                s1 = __hfma2(q2[5], kb[1], s1);
                s0 = __hfma2(q2[6], kb[2], s0);
                s1 = __hfma2(q2[7], kb[3], s1);
                float2 lf = __half22float2(__hadd2(s0, s1));
                float l = bp[jz] + lf.x + lf.y;
                float p = __expf(l);
                sum += p;
                float4 vA = vp[jz * 2 + e];
                float4 vB = vp[jz * 2 + 1 - e];
                const __half2* va = (const __half2*)&vA;
                const __half2* vb = (const __half2*)&vB;
                #pragma unroll
                for (int i = 0; i < 4; i++) {
                    float2 f0 = __half22float2(va[i]);
                    float2 f1 = __half22float2(vb[i]);
                    acc[2 * i]         += p * f0.x;
                    acc[2 * i + 1]     += p * f0.y;
                    acc[8 + 2 * i]     += p * f1.x;
                    acc[8 + 2 * i + 1] += p * f1.y;
                }
            }
        }
    }

    float inv = 1.f / sum;
    int n = h * 256 + w * 8 + z;
    #pragma unroll
    for (int d = 0; d < 16; d++)
        g_oT[(head * HD + d) * NPTS + n] = acc[d] * inv;
}

// ---------------------------------------------------------------------------
// Kernel 4: output projection. Tile 64c x 64n, 256 thr, micro 8c(4 pairs)x2n
// with f32x2. grid (128 n-tiles, 2 c-tiles). Double-buffered, kc=16.
// ---------------------------------------------------------------------------
__global__ __launch_bounds__(256) void proj_gemm(
        const float* __restrict__ Wo, const float* __restrict__ bo,
        float* __restrict__ outp) {
    int n0 = blockIdx.x * 64;
    int c0 = blockIdx.y * 64;
    int tid = threadIdx.x;

    __shared__ float As[2][16][64];   // Wo[j][c-slice]
    __shared__ float Bs[2][16][64];   // oT[j][n-slice]

    int tx = tid & 31, ty = tid >> 5;   // tx: n-pair (32), ty: c-octet (8)

    u64 acc[4][2];
    #pragma unroll
    for (int i = 0; i < 4; i++) { acc[i][0] = 0ull; acc[i][1] = 0ull; }

    float4 arA, arB;
    {
        int kk = tid >> 4, r4 = tid & 15;
        arA = *(const float4*)&Wo[kk * DIMC + c0 + r4 * 4];
        arB = *(const float4*)&g_oT[kk * NPTS + n0 + r4 * 4];
        *(float4*)&As[0][kk][r4 * 4] = arA;
        *(float4*)&Bs[0][kk][r4 * 4] = arB;
    }
    __syncthreads();

    for (int it = 0; it < 8; it++) {
        int cur = it & 1;
        if (it < 7) {
            int j0 = (it + 1) * 16;
            int kk = j0 + (tid >> 4), r4 = tid & 15;
            arA = *(const float4*)&Wo[kk * DIMC + c0 + r4 * 4];
            arB = *(const float4*)&g_oT[kk * NPTS + n0 + r4 * 4];
        }
        #pragma unroll
        for (int kk = 0; kk < 16; kk++) {
            ulonglong2 ca = *(const ulonglong2*)&As[cur][kk][ty * 8];
            ulonglong2 cb = *(const ulonglong2*)&As[cur][kk][ty * 8 + 4];
            float2 b2 = *(const float2*)&Bs[cur][kk][tx * 2];
            u64 pb0 = pk2(b2.x), pb1 = pk2(b2.y);
            ffma2(acc[0][0], ca.x, pb0); ffma2(acc[0][1], ca.x, pb1);
            ffma2(acc[1][0], ca.y, pb0); ffma2(acc[1][1], ca.y, pb1);
            ffma2(acc[2][0], cb.x, pb0); ffma2(acc[2][1], cb.x, pb1);
            ffma2(acc[3][0], cb.y, pb0); ffma2(acc[3][1], cb.y, pb1);
        }
        if (it < 7) {
            int nb = 1 - cur;
            int kk = tid >> 4, r4 = tid & 15;
            *(float4*)&As[nb][kk][r4 * 4] = arA;
            *(float4*)&Bs[nb][kk][r4 * 4] = arB;
            __syncthreads();
        }
    }

    #pragma unroll
    for (int cp = 0; cp < 4; cp++) {
        #pragma unroll
        for (int j = 0; j < 2; j++) {
            float2 f = up2(acc[cp][j]);
            int cA = c0 + ty * 8 + cp * 2;
            int nn = n0 + tx * 2 + j;
            outp[cA * NPTS + nn]       = f.x + bo[cA];
            outp[(cA + 1) * NPTS + nn] = f.y + bo[cA + 1];
        }
    }
}

// ---------------------------------------------------------------------------
extern "C" void kernel_launch(void* const* d_in, const int* in_sizes, int n_in,
                              void* d_out, int out_size) {
    const float* x    = (const float*)d_in[0];
    const float* skip = (const float*)d_in[1];
    const float* Wq   = (const float*)d_in[2];
    const float* bq   = (const float*)d_in[3];
    const float* Wk   = (const float*)d_in[4];
    const float* bk   = (const float*)d_in[5];
    const float* Wv   = (const float*)d_in[6];
    const float* bv   = (const float*)d_in[7];
    const float* rpb  = (const float*)d_in[8];
    const float* Wo   = (const float*)d_in[9];
    const float* bo   = (const float*)d_in[10];
    float* outp = (float*)d_out;

    const int attn_smem = (1536 + 1536) * 16 + 736 * 4;   // ~52KB
    cudaFuncSetAttribute(attn_kernel, cudaFuncAttributeMaxDynamicSharedMemorySize,
                         attn_smem);

    stats_kernel<<<256, 256>>>(x, skip);
    qkv_gemm<<<272, 256>>>(x, skip, Wq, bq, Wk, bk, Wv, bv);
    attn_kernel<<<dim3(8, 4, 8), 256, attn_smem>>>(rpb);
    proj_gemm<<<dim3(128, 2), 256>>>(Wo, bo, outp);
}

// round 9
// speedup vs baseline: 2.3012x; 1.3845x over previous
#include <cuda_runtime.h>
#include <cuda_fp16.h>

#define DIMC 128
#define HEADS 8
#define HD 16
#define HH 32
#define WW 32
#define ZZ 8
#define NPTS 8192   // 32*32*8
#define NXV 1024    // 16*16*4

// Scratch (device globals)
__device__ float   g_stats_x[DIMC * 2];
__device__ float   g_stats_s[DIMC * 2];
__device__ __half2 g_q16[HEADS * NXV * 8];     // [head][m][8 half2]
__device__ __half2 g_k16[HEADS * NPTS * 8];    // [head][n][8 half2]
__device__ __half2 g_v16[HEADS * NPTS * 8];    // [head][n][8 half2]
__device__ __half  g_o16[NPTS * DIMC];         // [n][j] row-major attn output

// ---------------------------------------------------------------------------
// Kernel 1: instance-norm statistics
// ---------------------------------------------------------------------------
__global__ void stats_kernel(const float* __restrict__ x,
                             const float* __restrict__ skip) {
    int c = blockIdx.x;
    const float* src; int n; float* dst;
    if (c < DIMC) { src = x + c * NXV;              n = NXV;  dst = g_stats_x + c * 2; }
    else          { src = skip + (c - DIMC) * NPTS; n = NPTS; dst = g_stats_s + (c - DIMC) * 2; }

    float s = 0.f, s2 = 0.f;
    for (int i = threadIdx.x; i < n; i += 256) {
        float v = src[i];
        s += v; s2 += v * v;
    }
    __shared__ float sh1[8], sh2[8];
    #pragma unroll
    for (int o = 16; o; o >>= 1) {
        s  += __shfl_down_sync(0xffffffffu, s,  o);
        s2 += __shfl_down_sync(0xffffffffu, s2, o);
    }
    int wid = threadIdx.x >> 5, lid = threadIdx.x & 31;
    if (lid == 0) { sh1[wid] = s; sh2[wid] = s2; }
    __syncthreads();
    if (threadIdx.x == 0) {
        float ts = 0.f, ts2 = 0.f;
        #pragma unroll
        for (int i = 0; i < 8; i++) { ts += sh1[i]; ts2 += sh2[i]; }
        float mean = ts / n;
        float var  = ts2 / n - mean * mean;
        dst[0] = mean;
        dst[1] = rsqrtf(var + 1e-5f);
    }
}

// ---- mma.sync m16n8k16 fp16 -> fp32 ---------------------------------------
__device__ __forceinline__ void mma16816(float* d, unsigned a0, unsigned a1,
                                         unsigned a2, unsigned a3,
                                         unsigned b0, unsigned b1) {
    asm volatile(
        "mma.sync.aligned.m16n8k16.row.col.f32.f16.f16.f32 "
        "{%0,%1,%2,%3},{%4,%5,%6,%7},{%8,%9},{%0,%1,%2,%3};"
        : "+f"(d[0]), "+f"(d[1]), "+f"(d[2]), "+f"(d[3])
        : "r"(a0), "r"(a1), "r"(a2), "r"(a3), "r"(b0), "r"(b1));
}

#define SSTR 136   // smem row stride (halves)

// ---------------------------------------------------------------------------
// Kernel 2: fused Q/K/V projection via tensor cores. grid 136:
//   blocks [0,64): K   [64,128): V   [128,136): Q
// One 128n x 128j x 128c tile per block. 8 warps, each 16 rows x 128 cols.
// A = normalized src transposed to smem [n][c] fp16; B = W transposed [j][c].
// All mma fragments are conflict-free LDS.32 (both operands k-contiguous).
// ---------------------------------------------------------------------------
__global__ __launch_bounds__(256) void qkv_mma(
        const float* __restrict__ x,  const float* __restrict__ skip,
        const float* __restrict__ Wq, const float* __restrict__ bq,
        const float* __restrict__ Wk, const float* __restrict__ bk,
        const float* __restrict__ Wv, const float* __restrict__ bv) {
    extern __shared__ __half sh[];
    __half (*sA)[SSTR] = (__half(*)[SSTR])sh;             // [n 128][c 128]
    __half (*sB)[SSTR] = (__half(*)[SSTR])(sh + 128 * SSTR);

    int bid = blockIdx.x;
    const float *src, *Wt, *bt, *stats;
    __half2* outp; int strideN; float scale; int n0;
    if (bid < 64) {
        src = skip; Wt = Wk; bt = bk; stats = g_stats_s;
        outp = g_k16; strideN = NPTS; scale = 1.f; n0 = bid * 128;
    } else if (bid < 128) {
        src = skip; Wt = Wv; bt = bv; stats = g_stats_s;
        outp = g_v16; strideN = NPTS; scale = 1.f; n0 = (bid - 64) * 128;
    } else {
        src = x; Wt = Wq; bt = bq; stats = g_stats_x;
        outp = g_q16; strideN = NXV; scale = 0.25f; n0 = (bid - 128) * 128;
    }
    int tid = threadIdx.x;

    // Stage A (normalize + transpose fp32 [c][n] -> fp16 [n][c])
    {
        int c = tid & 127, nh = (tid >> 7) * 64;
        float mu = stats[c * 2], rs = stats[c * 2 + 1];
        const float* sp = src + c * strideN + n0 + nh;
        #pragma unroll
        for (int i = 0; i < 16; i++) {
            float4 v = *(const float4*)(sp + i * 4);
            int n = nh + i * 4;
            sA[n + 0][c] = __float2half((v.x - mu) * rs);
            sA[n + 1][c] = __float2half((v.y - mu) * rs);
            sA[n + 2][c] = __float2half((v.z - mu) * rs);
            sA[n + 3][c] = __float2half((v.w - mu) * rs);
        }
        // Stage B (transpose W [c][j] -> [j][c])
        const float* wp = Wt + c * DIMC + nh;
        #pragma unroll
        for (int i = 0; i < 16; i++) {
            float4 v = *(const float4*)(wp + i * 4);
            int j = nh + i * 4;
            sB[j + 0][c] = __float2half(v.x);
            sB[j + 1][c] = __float2half(v.y);
            sB[j + 2][c] = __float2half(v.z);
            sB[j + 3][c] = __float2half(v.w);
        }
    }
    __syncthreads();

    int w = tid >> 5, t = tid & 31;
    int g = t >> 2, i2 = (t & 3) * 2;
    int mrow = w * 16;

    float acc[16][4];
    #pragma unroll
    for (int nt = 0; nt < 16; nt++)
        #pragma unroll
        for (int p = 0; p < 4; p++) acc[nt][p] = 0.f;

    #pragma unroll
    for (int kc = 0; kc < 8; kc++) {
        int k0 = kc * 16;
        unsigned a0 = *(const unsigned*)&sA[mrow + g][k0 + i2];
        unsigned a1 = *(const unsigned*)&sA[mrow + g + 8][k0 + i2];
        unsigned a2 = *(const unsigned*)&sA[mrow + g][k0 + i2 + 8];
        unsigned a3 = *(const unsigned*)&sA[mrow + g + 8][k0 + i2 + 8];
        #pragma unroll
        for (int nt = 0; nt < 16; nt++) {
            unsigned b0 = *(const unsigned*)&sB[nt * 8 + g][k0 + i2];
            unsigned b1 = *(const unsigned*)&sB[nt * 8 + g][k0 + i2 + 8];
            mma16816(acc[nt], a0, a1, a2, a3, b0, b1);
        }
    }

    // Epilogue: bias + scale, pack fp16 into [head][n][8 half2]
    int n1 = n0 + mrow + g;
    #pragma unroll
    for (int nt = 0; nt < 16; nt++) {
        int j = nt * 8 + i2;
        float2 bb = *(const float2*)&bt[j];
        int head = j >> 4;
        int jj = (j & 15) >> 1;
        outp[(head * strideN + n1) * 8 + jj] =
            __floats2half2_rn((acc[nt][0] + bb.x) * scale,
                              (acc[nt][1] + bb.y) * scale);
        outp[(head * strideN + n1 + 8) * 8 + jj] =
            __floats2half2_rn((acc[nt][2] + bb.x) * scale,
                              (acc[nt][3] + bb.y) * scale);
    }
}

// ---------------------------------------------------------------------------
// Kernel 3: neighborhood attention (known-good R3 config).
// Tile 4(h) x 8(w) x 8(z) = 256 threads, 1 thread per point.
// Halo 8x12x8 = 768 positions of fp16 k/v in swizzled smem (~52KB).
// No-max softmax, fp32 accumulator. Output fp16 [n][head*16+d] (for proj A).
// grid (8 hblk, 4 wblk, 8 heads).
// ---------------------------------------------------------------------------
#define WH 12   // w halo extent
__global__ __launch_bounds__(256, 4) void attn_kernel(const float* __restrict__ rpb) {
    extern __shared__ float smem[];
    float4* sk4 = (float4*)smem;              // 1536 float4 (768 pos * 2)
    float4* sv4 = sk4 + 1536;                 // 1536 float4
    float*  sb  = (float*)(sv4 + 1536);       // 729 bias

    int head = blockIdx.z;
    int h0 = blockIdx.x * 4, w0 = blockIdx.y * 8;
    int hlo = min(max(h0 - 2, 0), HH - 5);
    int wlo = min(max(w0 - 2, 0), WW - 5);
    int tid = threadIdx.x;

    for (int i = tid; i < 729; i += 256) sb[i] = rpb[head * 729 + i];

    const float4* gk4 = (const float4*)g_k16 + head * (NPTS * 2);
    const float4* gv4 = (const float4*)g_v16 + head * (NPTS * 2);
    #pragma unroll
    for (int it = 0; it < 6; it++) {
        int idx = it * 256 + tid;             // 1536 (pos,d4) pairs
        int d4 = idx & 1, pos = idx >> 1;
        int col = pos >> 3, z1 = pos & 7;
        int wh = col / WH, wwi = col - wh * WH;
        int gh = min(hlo + wh, HH - 1);
        int gw = min(wlo + wwi, WW - 1);
        int n = gh * 256 + gw * 8 + z1;
        int s = pos * 2 + (d4 ^ (col & 1));   // XOR swizzle
        sk4[s] = gk4[n * 2 + d4];
        sv4[s] = gv4[n * 2 + d4];
    }
    __syncthreads();

    int z = tid & 7, dw = (tid >> 3) & 7, dh = tid >> 6;
    int h = h0 + dh, w = w0 + dw;
    int sh = min(max(h - 2, 0), HH - 5);
    int sw = min(max(w - 2, 0), WW - 5);
    int sz = min(max(z - 2, 0), ZZ - 5);
    int m = (h >> 1) * 64 + (w >> 1) * 4 + (z >> 1);

    __half2 q2[8];
    {
        const float4* gq4 = (const float4*)g_q16 + (head * NXV + m) * 2;
        float4 qA = gq4[0], qB = gq4[1];
        const __half2* qa = (const __half2*)&qA;
        const __half2* qb = (const __half2*)&qB;
        #pragma unroll
        for (int i = 0; i < 4; i++) { q2[i] = qa[i]; q2[4 + i] = qb[i]; }
    }

    int bh = sh - h + 4, bw = sw - w + 4, bz = sz - z + 4;

    float sum = 0.f;
    float acc[16];
    #pragma unroll
    for (int d = 0; d < 16; d++) acc[d] = 0.f;

    for (int jh = 0; jh < 5; jh++) {
        int colh = (sh + jh - hlo) * WH;
        const float* bph = sb + (bh + jh) * 81 + bz;
        for (int jw = 0; jw < 5; jw++) {
            int col = colh + (sw + jw - wlo);
            int e = col & 1;
            const float4* kp = sk4 + col * 16 + sz * 2;
            const float4* vp = sv4 + col * 16 + sz * 2;
            const float* bp = bph + (bw + jw) * 9;
            #pragma unroll
            for (int jz = 0; jz < 5; jz++) {
                float4 kA = kp[jz * 2 + e];
                float4 kB = kp[jz * 2 + 1 - e];
                const __half2* ka = (const __half2*)&kA;
                const __half2* kb = (const __half2*)&kB;
                __half2 s0 = __hmul2(q2[0], ka[0]);
                __half2 s1 = __hmul2(q2[1], ka[1]);
                s0 = __hfma2(q2[2], ka[2], s0);
                s1 = __hfma2(q2[3], ka[3], s1);
                s0 = __hfma2(q2[4], kb[0], s0);
                s1 = __hfma2(q2[5], kb[1], s1);
                s0 = __hfma2(q2[6], kb[2], s0);
                s1 = __hfma2(q2[7], kb[3], s1);
                float2 lf = __half22float2(__hadd2(s0, s1));
                float l = bp[jz] + lf.x + lf.y;
                float p = __expf(l);
                sum += p;
                float4 vA = vp[jz * 2 + e];
                float4 vB = vp[jz * 2 + 1 - e];
                const __half2* va = (const __half2*)&vA;
                const __half2* vb = (const __half2*)&vB;
                #pragma unroll
                for (int i = 0; i < 4; i++) {
                    float2 f0 = __half22float2(va[i]);
                    float2 f1 = __half22float2(vb[i]);
                    acc[2 * i]         += p * f0.x;
                    acc[2 * i + 1]     += p * f0.y;
                    acc[8 + 2 * i]     += p * f1.x;
                    acc[8 + 2 * i + 1] += p * f1.y;
                }
            }
        }
    }

    float inv = 1.f / sum;
    int n = h * 256 + w * 8 + z;
    __half2 o2[8];
    #pragma unroll
    for (int d = 0; d < 8; d++)
        o2[d] = __floats2half2_rn(acc[2 * d] * inv, acc[2 * d + 1] * inv);
    float4* dst = (float4*)(g_o16 + n * DIMC + head * 16);
    dst[0] = ((const float4*)o2)[0];
    dst[1] = ((const float4*)o2)[1];
}

// ---------------------------------------------------------------------------
// Kernel 4: output projection via tensor cores. grid 128 =
// (64 n-tiles) x (2 c-halves). Tile 128n x 64c x 128k.
// A = g_o16 [n][j] (direct vectorized copy), B = Wo transposed [c][j].
// 8 warps x (16 rows x 64 cols). fp32 output [c][n] + bias.
// ---------------------------------------------------------------------------
__global__ __launch_bounds__(256) void proj_mma(
        const float* __restrict__ Wo, const float* __restrict__ bo,
        float* __restrict__ outp) {
    extern __shared__ __half sh[];
    __half (*sA)[SSTR] = (__half(*)[SSTR])sh;             // [n 128][j 128]
    __half (*sB)[SSTR] = (__half(*)[SSTR])(sh + 128 * SSTR); // [c 64][j 128]

    int n0 = (blockIdx.x >> 1) * 128;
    int c0 = (blockIdx.x & 1) * 64;
    int tid = threadIdx.x;

    // Stage A: copy fp16 [n][j]
    {
        int n = tid & 127, jh = (tid >> 7) * 64;
        const float4* gA = (const float4*)(g_o16 + (n0 + n) * DIMC + jh);
        float4* dA = (float4*)&sA[n][jh];
        #pragma unroll
        for (int i = 0; i < 8; i++) dA[i] = gA[i];
    }
    // Stage B: transpose Wo [j][c] -> [c][j] fp16
    {
        int k = tid & 127, chh = (tid >> 7) * 32;
        const float* wp = Wo + k * DIMC + c0 + chh;
        #pragma unroll
        for (int i = 0; i < 8; i++) {
            float4 v = *(const float4*)(wp + i * 4);
            int cc = chh + i * 4;
            sB[cc + 0][k] = __float2half(v.x);
            sB[cc + 1][k] = __float2half(v.y);
            sB[cc + 2][k] = __float2half(v.z);
            sB[cc + 3][k] = __float2half(v.w);
        }
    }
    __syncthreads();

    int w = tid >> 5, t = tid & 31;
    int g = t >> 2, i2 = (t & 3) * 2;
    int mrow = w * 16;

    float acc[8][4];
    #pragma unroll
    for (int nt = 0; nt < 8; nt++)
        #pragma unroll
        for (int p = 0; p < 4; p++) acc[nt][p] = 0.f;

    #pragma unroll
    for (int kc = 0; kc < 8; kc++) {
        int k0 = kc * 16;
        unsigned a0 = *(const unsigned*)&sA[mrow + g][k0 + i2];
        unsigned a1 = *(const unsigned*)&sA[mrow + g + 8][k0 + i2];
        unsigned a2 = *(const unsigned*)&sA[mrow + g][k0 + i2 + 8];
        unsigned a3 = *(const unsigned*)&sA[mrow + g + 8][k0 + i2 + 8];
        #pragma unroll
        for (int nt = 0; nt < 8; nt++) {
            unsigned b0 = *(const unsigned*)&sB[nt * 8 + g][k0 + i2];
            unsigned b1 = *(const unsigned*)&sB[nt * 8 + g][k0 + i2 + 8];
            mma16816(acc[nt], a0, a1, a2, a3, b0, b1);
        }
    }

    // Epilogue: out[c][n] fp32 + bias (transposed scatter, 32B sectors)
    int n1 = n0 + mrow + g;
    #pragma unroll
    for (int nt = 0; nt < 8; nt++) {
        int c = c0 + nt * 8 + i2;
        float2 bb = *(const float2*)&bo[c];
        outp[c * NPTS + n1]           = acc[nt][0] + bb.x;
        outp[(c + 1) * NPTS + n1]     = acc[nt][1] + bb.y;
        outp[c * NPTS + n1 + 8]       = acc[nt][2] + bb.x;
        outp[(c + 1) * NPTS + n1 + 8] = acc[nt][3] + bb.y;
    }
}

// ---------------------------------------------------------------------------
extern "C" void kernel_launch(void* const* d_in, const int* in_sizes, int n_in,
                              void* d_out, int out_size) {
    const float* x    = (const float*)d_in[0];
    const float* skip = (const float*)d_in[1];
    const float* Wq   = (const float*)d_in[2];
    const float* bq   = (const float*)d_in[3];
    const float* Wk   = (const float*)d_in[4];
    const float* bk   = (const float*)d_in[5];
    const float* Wv   = (const float*)d_in[6];
    const float* bv   = (const float*)d_in[7];
    const float* rpb  = (const float*)d_in[8];
    const float* Wo   = (const float*)d_in[9];
    const float* bo   = (const float*)d_in[10];
    float* outp = (float*)d_out;

    const int attn_smem = (1536 + 1536) * 16 + 736 * 4;       // ~52KB
    const int qkv_smem  = 256 * SSTR * sizeof(__half);        // ~69.6KB
    const int proj_smem = 192 * SSTR * sizeof(__half);        // ~52.2KB
    cudaFuncSetAttribute(attn_kernel, cudaFuncAttributeMaxDynamicSharedMemorySize,
                         attn_smem);
    cudaFuncSetAttribute(qkv_mma, cudaFuncAttributeMaxDynamicSharedMemorySize,
                         qkv_smem);
    cudaFuncSetAttribute(proj_mma, cudaFuncAttributeMaxDynamicSharedMemorySize,
                         proj_smem);

    stats_kernel<<<256, 256>>>(x, skip);
    qkv_mma<<<136, 256, qkv_smem>>>(x, skip, Wq, bq, Wk, bk, Wv, bv);
    attn_kernel<<<dim3(8, 4, 8), 256, attn_smem>>>(rpb);
    proj_mma<<<128, 256, proj_smem>>>(Wo, bo, outp);
}